// round 14
// baseline (speedup 1.0000x reference)
#include <cuda_runtime.h>
#include <cuda_fp16.h>

#define NN 100000
#define NE 1600000
#define NG 128
#define NF 128
#define SCAN_BS 512
#define SCAN_BLOCKS ((NN + SCAN_BS - 1) / SCAN_BS)   // 196
#define WST 136                                       // padded k-stride for Ws (halves)

// ---------------- scratch ----------------
__device__ int    g_deg_out[2][NN];
__device__ int    g_deg_in [2][NN];
__device__ int    g_off    [2][NN + 1];
__device__ int    g_cursor [2][NN + 1];
__device__ int    g_bsums  [2][256];
__device__ int    g_esrc   [2][NE];
__device__ __half g_P      [2][NN * NF];      // 25.6 MB each: (feat*c_out)@W in fp16
__device__ __half g_Wh     [NF * WST];        // W transposed (n-major, k-contig, padded)
__device__ float  g_gsum   [2][NG * NF];
__device__ int    g_gcnt   [2][NG];

// streaming load with evict-first L2 policy (createpolicy + cache_hint form:
// legal at any width, unlike the immediate .L2::evict_first qualifier)
__device__ __forceinline__ float2 ldg_ef2(const float* p) {
    float2 r;
    asm volatile(
        "{\n\t"
        ".reg .b64 pol;\n\t"
        "createpolicy.fractional.L2::evict_first.b64 pol, 1.0;\n\t"
        "ld.global.nc.L2::cache_hint.v2.f32 {%0,%1}, [%2], pol;\n\t"
        "}"
        : "=f"(r.x), "=f"(r.y) : "l"(p));
    return r;
}

// ---------------- kernels ----------------
__global__ void zw_kernel(const float* __restrict__ W) {
    int br = blockIdx.y;
    int i = blockIdx.x * blockDim.x + threadIdx.x;
    if (i < NN) { g_deg_out[br][i] = 0; g_deg_in[br][i] = 0; }
    if (i < NG * NF) g_gsum[br][i] = 0.f;
    if (i < NG) g_gcnt[br][i] = 0;
    if (br == 0 && i < NF * NF) {
        int k = i >> 7, n = i & 127;
        g_Wh[n * WST + k] = __float2half_rn(W[i]);
    }
}

__global__ void degree_kernel(const int* __restrict__ s1, const int* __restrict__ d1,
                              const int* __restrict__ s2, const int* __restrict__ d2) {
    int br = blockIdx.y;
    const int* s = br ? s2 : s1;
    const int* d = br ? d2 : d1;
    int i = blockIdx.x * blockDim.x + threadIdx.x;
    if (i < NE) {
        atomicAdd(&g_deg_out[br][s[i]], 1);
        atomicAdd(&g_deg_in [br][d[i]], 1);
    }
}

__global__ void scan1_kernel() {
    int br = blockIdx.y;
    __shared__ int sh[SCAN_BS];
    int tid = threadIdx.x;
    int i = blockIdx.x * SCAN_BS + tid;
    int v = (i < NN) ? g_deg_in[br][i] : 0;
    sh[tid] = v;
    __syncthreads();
    for (int o = 1; o < SCAN_BS; o <<= 1) {
        int t = (tid >= o) ? sh[tid - o] : 0;
        __syncthreads();
        sh[tid] += t;
        __syncthreads();
    }
    if (i < NN) g_off[br][i + 1] = sh[tid];
    if (tid == SCAN_BS - 1) g_bsums[br][blockIdx.x] = sh[tid];
}

__global__ void scan2_kernel() {
    int br = blockIdx.y;
    __shared__ int sh[256];
    int tid = threadIdx.x;
    int v = (tid < SCAN_BLOCKS) ? g_bsums[br][tid] : 0;
    sh[tid] = v;
    __syncthreads();
    for (int o = 1; o < 256; o <<= 1) {
        int t = (tid >= o) ? sh[tid - o] : 0;
        __syncthreads();
        sh[tid] += t;
        __syncthreads();
    }
    if (tid < SCAN_BLOCKS) g_bsums[br][tid] = sh[tid] - v;   // exclusive
}

__global__ void scan3_kernel() {
    int br = blockIdx.y;
    int i = blockIdx.x * SCAN_BS + threadIdx.x;
    if (i < NN) {
        int v = g_off[br][i + 1] + g_bsums[br][i >> 9];
        g_off[br][i + 1] = v;
        g_cursor[br][i + 1] = v;
    }
    if (i == 0) { g_off[br][0] = 0; g_cursor[br][0] = 0; }
}

__global__ void scatter_kernel(const int* __restrict__ s1, const int* __restrict__ d1,
                               const int* __restrict__ s2, const int* __restrict__ d2) {
    int br = blockIdx.y;
    const int* s = br ? s2 : s1;
    const int* d = br ? d2 : d1;
    int i = blockIdx.x * blockDim.x + threadIdx.x;
    if (i < NE) {
        int p = atomicAdd(&g_cursor[br][d[i]], 1);
        g_esrc[br][p] = s[i];
    }
}

// ---------------- tensor-core GEMM (per-branch): P = (feat*c_out)@W -> fp16 ----------------
__device__ __forceinline__ unsigned h2u(__half2 h) { return *reinterpret_cast<unsigned*>(&h); }

__global__ __launch_bounds__(256) void gemm_mma_kernel(
        int br, const float* __restrict__ feat) {
    extern __shared__ __half Ws[];    // [128 n][WST k]
    const int tid = threadIdx.x;

    {   // copy pre-transposed fp16 W into smem (vectorized)
        const uint4* s = reinterpret_cast<const uint4*>(g_Wh);
        uint4* dsm = reinterpret_cast<uint4*>(Ws);
        #pragma unroll
        for (int i = tid; i < NF * WST * 2 / 16; i += 256) dsm[i] = s[i];
    }
    __syncthreads();

    const int w = tid >> 5, lane = tid & 31;
    const int g = lane >> 2, tg = lane & 3;
    const int base = blockIdx.x * 128;
    const int row0 = base + w * 16 + g;
    const int row1 = row0 + 8;
    const bool v0 = row0 < NN, v1 = row1 < NN;
    const float c0 = v0 ? rsqrtf(fmaxf((float)g_deg_out[br][row0], 1.f)) : 0.f;
    const float c1 = v1 ? rsqrtf(fmaxf((float)g_deg_out[br][row1], 1.f)) : 0.f;

    unsigned a[8][4];
    const float2 z2 = make_float2(0.f, 0.f);
    #pragma unroll
    for (int kc = 0; kc < 8; kc++) {
        int k0 = kc * 16 + tg * 2;
        float2 x0 = v0 ? ldg_ef2(&feat[row0 * 128 + k0])     : z2;
        float2 x1 = v1 ? ldg_ef2(&feat[row1 * 128 + k0])     : z2;
        float2 x2 = v0 ? ldg_ef2(&feat[row0 * 128 + k0 + 8]) : z2;
        float2 x3 = v1 ? ldg_ef2(&feat[row1 * 128 + k0 + 8]) : z2;
        a[kc][0] = h2u(__floats2half2_rn(x0.x * c0, x0.y * c0));
        a[kc][1] = h2u(__floats2half2_rn(x1.x * c1, x1.y * c1));
        a[kc][2] = h2u(__floats2half2_rn(x2.x * c0, x2.y * c0));
        a[kc][3] = h2u(__floats2half2_rn(x3.x * c1, x3.y * c1));
    }

    __half* __restrict__ P = g_P[br];
    #pragma unroll
    for (int nt = 0; nt < 16; nt++) {
        float d0 = 0.f, d1 = 0.f, d2 = 0.f, d3 = 0.f;
        const __half* wrow = &Ws[(nt * 8 + g) * WST + tg * 2];
        #pragma unroll
        for (int kc = 0; kc < 8; kc++) {
            unsigned b0 = *reinterpret_cast<const unsigned*>(wrow + kc * 16);
            unsigned b1 = *reinterpret_cast<const unsigned*>(wrow + kc * 16 + 8);
            asm volatile(
                "mma.sync.aligned.m16n8k16.row.col.f32.f16.f16.f32 "
                "{%0,%1,%2,%3}, {%4,%5,%6,%7}, {%8,%9}, {%0,%1,%2,%3};"
                : "+f"(d0), "+f"(d1), "+f"(d2), "+f"(d3)
                : "r"(a[kc][0]), "r"(a[kc][1]), "r"(a[kc][2]), "r"(a[kc][3]),
                  "r"(b0), "r"(b1));
        }
        int col = nt * 8 + tg * 2;
        if (v0) *reinterpret_cast<__half2*>(&P[row0 * 128 + col]) = __floats2half2_rn(d0, d1);
        if (v1) *reinterpret_cast<__half2*>(&P[row1 * 128 + col]) = __floats2half2_rn(d2, d3);
    }
}

// ---------------- gather + epilogue (per-branch; R5 inner loop, measured best) ----------------
__global__ __launch_bounds__(256) void agg_epilogue_kernel(
        int br, const int* __restrict__ gid, const float* __restrict__ bias) {
    const int w = threadIdx.x >> 5, lane = threadIdx.x & 31;
    const int* __restrict__ off  = g_off[br];
    const int* __restrict__ esrc = g_esrc[br];
    const uint2* __restrict__ Pu = reinterpret_cast<const uint2*>(g_P[br]);
    float* gsum = g_gsum[br];
    int*   gcnt = g_gcnt[br];
    const float4 bv = reinterpret_cast<const float4*>(bias)[lane];

    float4 racc = make_float4(0.f, 0.f, 0.f, 0.f);
    int rcnt = 0;
    int curg = -1;
    const int baseN = blockIdx.x * 256;

    for (int t = 0; t < 32; t++) {
        int node = baseN + t * 8 + w;
        if (node >= NN) break;                      // monotone in t
        int g = gid[node];
        if (g != curg) {
            if (curg >= 0) {
                atomicAdd(&gsum[curg * 128 + lane * 4 + 0], racc.x);
                atomicAdd(&gsum[curg * 128 + lane * 4 + 1], racc.y);
                atomicAdd(&gsum[curg * 128 + lane * 4 + 2], racc.z);
                atomicAdd(&gsum[curg * 128 + lane * 4 + 3], racc.w);
                if (lane == 0) atomicAdd(&gcnt[curg], rcnt);
                racc = make_float4(0.f, 0.f, 0.f, 0.f);
                rcnt = 0;
            }
            curg = g;
        }
        int beg = off[node], end = off[node + 1];
        float ax = 0.f, ay = 0.f, az = 0.f, aw = 0.f;
        int e = beg;
        while (e < end) {
            int cnt = min(32, end - e);
            int sid = (lane < cnt) ? esrc[e + lane] : 0;
            int j = 0;
            for (; j + 4 <= cnt; j += 4) {
                int s0 = __shfl_sync(0xffffffffu, sid, j + 0);
                int s1 = __shfl_sync(0xffffffffu, sid, j + 1);
                int s2 = __shfl_sync(0xffffffffu, sid, j + 2);
                int s3 = __shfl_sync(0xffffffffu, sid, j + 3);
                uint2 v0 = Pu[s0 * 32 + lane];
                uint2 v1 = Pu[s1 * 32 + lane];
                uint2 v2 = Pu[s2 * 32 + lane];
                uint2 v3 = Pu[s3 * 32 + lane];
                #define ACC_V(v) { \
                    const __half2* hp = reinterpret_cast<const __half2*>(&(v)); \
                    float2 fa = __half22float2(hp[0]); \
                    float2 fb = __half22float2(hp[1]); \
                    ax += fa.x; ay += fa.y; az += fb.x; aw += fb.y; }
                ACC_V(v0) ACC_V(v1) ACC_V(v2) ACC_V(v3)
            }
            for (; j < cnt; j++) {
                int s0 = __shfl_sync(0xffffffffu, sid, j);
                uint2 v0 = Pu[s0 * 32 + lane];
                ACC_V(v0)
                #undef ACC_V
            }
            e += cnt;
        }
        float cin = rsqrtf(fmaxf((float)(end - beg), 1.f));
        float hx = ax * cin + bv.x;
        float hy = ay * cin + bv.y;
        float hz = az * cin + bv.z;
        float hw = aw * cin + bv.w;
        float p = hx * hx + hy * hy + hz * hz + hw * hw;
        #pragma unroll
        for (int o = 16; o > 0; o >>= 1) p += __shfl_xor_sync(0xffffffffu, p, o);
        float inv = 1.f / fmaxf(sqrtf(p), 1e-12f);
        racc.x += 1.f / (1.f + __expf(-hx * inv));   // relu(sigmoid)==sigmoid
        racc.y += 1.f / (1.f + __expf(-hy * inv));
        racc.z += 1.f / (1.f + __expf(-hz * inv));
        racc.w += 1.f / (1.f + __expf(-hw * inv));
        rcnt++;
    }
    if (curg >= 0) {
        atomicAdd(&gsum[curg * 128 + lane * 4 + 0], racc.x);
        atomicAdd(&gsum[curg * 128 + lane * 4 + 1], racc.y);
        atomicAdd(&gsum[curg * 128 + lane * 4 + 2], racc.z);
        atomicAdd(&gsum[curg * 128 + lane * 4 + 3], racc.w);
        if (lane == 0) atomicAdd(&gcnt[curg], rcnt);
    }
}

__global__ void final_kernel(const float* __restrict__ Wc, const float* __restrict__ bc,
                             float* __restrict__ out) {
    __shared__ float h1[128], h2[128];
    __shared__ float rsum[2];
    int g = blockIdx.x, t = threadIdx.x;   // 64 threads
    float c1 = fmaxf((float)g_gcnt[0][g], 1.f);
    float c2 = fmaxf((float)g_gcnt[1][g], 1.f);
    for (int k = t; k < 128; k += 64) {
        h1[k] = g_gsum[0][g * 128 + k] / c1;
        h2[k] = g_gsum[1][g * 128 + k] / c2;
    }
    __syncthreads();
    float l1 = bc[t], l2 = bc[t];
    #pragma unroll 4
    for (int k = 0; k < 128; k++) {
        float w = Wc[k * 64 + t];
        l1 = fmaf(h1[k], w, l1);
        l2 = fmaf(h2[k], w, l2);
    }
    float d = l1 - l2 + 1e-6f;
    float sq = d * d;
    for (int o = 16; o > 0; o >>= 1) sq += __shfl_down_sync(0xffffffffu, sq, o);
    if ((t & 31) == 0) rsum[t >> 5] = sq;
    __syncthreads();
    if (t == 0) out[g] = sqrtf(rsum[0] + rsum[1]);
}

// ---------------- launch: CSR chain overlaps the two gemms; aggs per branch ----------------
extern "C" void kernel_launch(void* const* d_in, const int* in_sizes, int n_in,
                              void* d_out, int out_size) {
    const float* feat1 = (const float*)d_in[0];
    const float* feat2 = (const float*)d_in[1];
    const int* src1 = (const int*)d_in[2];
    const int* dst1 = (const int*)d_in[3];
    const int* gid1 = (const int*)d_in[4];
    const int* src2 = (const int*)d_in[5];
    const int* dst2 = (const int*)d_in[6];
    const int* gid2 = (const int*)d_in[7];
    const float* W  = (const float*)d_in[8];
    const float* b  = (const float*)d_in[9];
    const float* Wc = (const float*)d_in[10];
    const float* bc = (const float*)d_in[11];
    float* out = (float*)d_out;

    const int EB = (NE + 255) / 256;     // 6250
    const int NB = (NN + 255) / 256;     // 391
    const int GB = (NN + 127) / 128;     // 782
    const int SMEM_MMA = NF * WST * 2;   // 34816 B

    cudaStream_t s2;
    cudaStreamCreateWithFlags(&s2, cudaStreamNonBlocking);
    cudaEvent_t evA, evB;
    cudaEventCreateWithFlags(&evA, cudaEventDisableTiming);
    cudaEventCreateWithFlags(&evB, cudaEventDisableTiming);

    zw_kernel     <<<dim3(NB, 2), 256>>>(W);
    degree_kernel <<<dim3(EB, 2), 256>>>(src1, dst1, src2, dst2);
    cudaEventRecord(evA, 0);

    // CSR chain on side stream (needs deg_in only)
    cudaStreamWaitEvent(s2, evA, 0);
    scan1_kernel  <<<dim3(SCAN_BLOCKS, 2), SCAN_BS, 0, s2>>>();
    scan2_kernel  <<<dim3(1, 2), 256, 0, s2>>>();
    scan3_kernel  <<<dim3(SCAN_BLOCKS, 2), SCAN_BS, 0, s2>>>();
    scatter_kernel<<<dim3(EB, 2), 256, 0, s2>>>(src1, dst1, src2, dst2);
    cudaEventRecord(evB, s2);

    // gemms on main stream (branch 1 first so branch 0's P is freshest for agg0)
    gemm_mma_kernel<<<GB, 256, SMEM_MMA>>>(1, feat2);
    gemm_mma_kernel<<<GB, 256, SMEM_MMA>>>(0, feat1);

    cudaStreamWaitEvent(0, evB, 0);
    agg_epilogue_kernel<<<NB, 256>>>(0, gid1, b);
    agg_epilogue_kernel<<<NB, 256>>>(1, gid2, b);
    final_kernel  <<<NG, 64>>>(Wc, bc, out);
}

// round 15
// speedup vs baseline: 1.2451x; 1.2451x over previous
#include <cuda_runtime.h>
#include <cuda_fp16.h>

#define NN 100000
#define NE 1600000
#define NG 128
#define NF 128
#define WST 136                       // padded k-stride for Ws (halves)
#define SC_BS 512
#define SC_TILE 2048                  // 512 threads * 4 elems
#define SC_NB ((NN + SC_TILE - 1) / SC_TILE)   // 49

// ---------------- scratch ----------------
__device__ int    g_deg_out[2][NN];
__device__ int    g_deg_in [2][NN];
__device__ int    g_off    [2][NN + 1];       // off[0]=0, off[i+1]=inclusive prefix
__device__ int    g_cursor [2][NN + 1];       // cursor[i] = off[i] (scatter cursors)
__device__ unsigned long long g_state[2][SC_NB];   // lookback: status(2b)<<62 | sum
__device__ int    g_esrc   [2][NE];
__device__ __half g_P      [2][NN * NF];      // 25.6 MB each: (feat*c_out)@W in fp16
__device__ __half g_Wh     [NF * WST];        // W transposed (n-major, k-contig, padded)
__device__ float  g_gsum   [2][NG * NF];
__device__ int    g_gcnt   [2][NG];

// ---------------- kernels (gridDim.y = branch) ----------------
// zero scratch + convert W to transposed fp16 (branch 0 blocks only)
__global__ void zw_kernel(const float* __restrict__ W) {
    int br = blockIdx.y;
    int i = blockIdx.x * blockDim.x + threadIdx.x;
    if (i < NN) { g_deg_out[br][i] = 0; g_deg_in[br][i] = 0; }
    if (i < NG * NF) g_gsum[br][i] = 0.f;
    if (i < NG) g_gcnt[br][i] = 0;
    if (i < SC_NB) g_state[br][i] = 0ULL;
    if (br == 0 && i < NF * NF) {
        int k = i >> 7, n = i & 127;
        g_Wh[n * WST + k] = __float2half_rn(W[i]);
    }
}

__global__ void degree_kernel(const int* __restrict__ s1, const int* __restrict__ d1,
                              const int* __restrict__ s2, const int* __restrict__ d2) {
    int br = blockIdx.y;
    const int* s = br ? s2 : s1;
    const int* d = br ? d2 : d1;
    int i = blockIdx.x * blockDim.x + threadIdx.x;
    if (i < NE) {
        atomicAdd(&g_deg_out[br][s[i]], 1);
        atomicAdd(&g_deg_in [br][d[i]], 1);
    }
}

// ---------------- single-pass decoupled-lookback scan (replaces scan1/2/3) ----------------
// Produces R5's exact layout: off[0]=0, off[i+1]=inclusive prefix; cursor[i]=off[i].
__global__ __launch_bounds__(SC_BS) void scanLB_kernel() {
    __shared__ int wsum[16];
    __shared__ int sh_pfx;
    int br = blockIdx.y, bid = blockIdx.x, tid = threadIdx.x;
    int base = bid * SC_TILE + tid * 4;
    int4 v = make_int4(0, 0, 0, 0);
    if (base + 3 < NN) v = *reinterpret_cast<const int4*>(&g_deg_in[br][base]);
    else if (base < NN) {
        v.x = g_deg_in[br][base];
        if (base + 1 < NN) v.y = g_deg_in[br][base + 1];
        if (base + 2 < NN) v.z = g_deg_in[br][base + 2];
    }
    int t = v.x + v.y + v.z + v.w;
    int lane = tid & 31, w = tid >> 5;
    int inc = t;
    #pragma unroll
    for (int o = 1; o < 32; o <<= 1) {
        int n = __shfl_up_sync(0xffffffffu, inc, o);
        if (lane >= o) inc += n;
    }
    if (lane == 31) wsum[w] = inc;
    __syncthreads();
    if (w == 0) {
        int s = (lane < 16) ? wsum[lane] : 0;
        #pragma unroll
        for (int o = 1; o < 16; o <<= 1) {
            int n = __shfl_up_sync(0xffffffffu, s, o);
            if (lane >= o) s += n;
        }
        if (lane < 16) wsum[lane] = s;
    }
    __syncthreads();

    if (tid == 0) {
        unsigned long long blkagg = (unsigned long long)wsum[15];
        if (bid == 0) {
            atomicExch(&g_state[br][0], (2ULL << 62) | blkagg);
            sh_pfx = 0;
        } else {
            atomicExch(&g_state[br][bid], (1ULL << 62) | blkagg);
            long long pfx = 0;
            for (int p = bid - 1; p >= 0; ) {
                unsigned long long s;
                do { s = atomicAdd(&g_state[br][p], 0ULL); } while ((s >> 62) == 0);
                pfx += (long long)(s & 0x3FFFFFFFFFFFFFFFULL);
                if ((s >> 62) == 2ULL) break;
                p--;
            }
            sh_pfx = (int)pfx;
            atomicExch(&g_state[br][bid],
                       (2ULL << 62) | (unsigned long long)(pfx + (long long)blkagg));
        }
    }
    __syncthreads();

    int excl = sh_pfx + (w ? wsum[w - 1] : 0) + inc - t;
    int i0 = excl + v.x, i1 = i0 + v.y, i2 = i1 + v.z, i3 = i2 + v.w;
    // R5 layout: off[i+1] = inclusive prefix at i; cursor[i+1] identical
    if (base < NN)     { g_off[br][base + 1] = i0; g_cursor[br][base + 1] = i0; }
    if (base + 1 < NN) { g_off[br][base + 2] = i1; g_cursor[br][base + 2] = i1; }
    if (base + 2 < NN) { g_off[br][base + 3] = i2; g_cursor[br][base + 3] = i2; }
    if (base + 3 < NN) { g_off[br][base + 4] = i3; g_cursor[br][base + 4] = i3; }
    if (base == 0 && tid == 0) { g_off[br][0] = 0; g_cursor[br][0] = 0; }
}

__global__ void scatter_kernel(const int* __restrict__ s1, const int* __restrict__ d1,
                               const int* __restrict__ s2, const int* __restrict__ d2) {
    int br = blockIdx.y;
    const int* s = br ? s2 : s1;
    const int* d = br ? d2 : d1;
    int i = blockIdx.x * blockDim.x + threadIdx.x;
    if (i < NE) {
        int p = atomicAdd(&g_cursor[br][d[i]], 1);
        g_esrc[br][p] = s[i];
    }
}

// ---------------- tensor-core GEMM: P = (feat * deg_out^-1/2) @ W -> fp16 ----------------
__device__ __forceinline__ unsigned h2u(__half2 h) { return *reinterpret_cast<unsigned*>(&h); }

__global__ __launch_bounds__(256) void gemm_mma_kernel(
        const float* __restrict__ f1, const float* __restrict__ f2) {
    extern __shared__ __half Ws[];    // [128 n][WST k]
    int br = blockIdx.y;
    const float* __restrict__ feat = br ? f2 : f1;
    const int tid = threadIdx.x;

    {   // copy pre-transposed fp16 W into smem (vectorized)
        const uint4* s = reinterpret_cast<const uint4*>(g_Wh);
        uint4* dsm = reinterpret_cast<uint4*>(Ws);
        #pragma unroll
        for (int i = tid; i < NF * WST * 2 / 16; i += 256) dsm[i] = s[i];
    }
    __syncthreads();

    const int w = tid >> 5, lane = tid & 31;
    const int g = lane >> 2, tg = lane & 3;
    const int base = blockIdx.x * 128;
    const int row0 = base + w * 16 + g;
    const int row1 = row0 + 8;
    const bool v0 = row0 < NN, v1 = row1 < NN;
    const float c0 = v0 ? rsqrtf(fmaxf((float)g_deg_out[br][row0], 1.f)) : 0.f;
    const float c1 = v1 ? rsqrtf(fmaxf((float)g_deg_out[br][row1], 1.f)) : 0.f;

    unsigned a[8][4];
    const float2 z2 = make_float2(0.f, 0.f);
    #pragma unroll
    for (int kc = 0; kc < 8; kc++) {
        int k0 = kc * 16 + tg * 2;
        float2 x0 = v0 ? *reinterpret_cast<const float2*>(&feat[row0 * 128 + k0])     : z2;
        float2 x1 = v1 ? *reinterpret_cast<const float2*>(&feat[row1 * 128 + k0])     : z2;
        float2 x2 = v0 ? *reinterpret_cast<const float2*>(&feat[row0 * 128 + k0 + 8]) : z2;
        float2 x3 = v1 ? *reinterpret_cast<const float2*>(&feat[row1 * 128 + k0 + 8]) : z2;
        a[kc][0] = h2u(__floats2half2_rn(x0.x * c0, x0.y * c0));
        a[kc][1] = h2u(__floats2half2_rn(x1.x * c1, x1.y * c1));
        a[kc][2] = h2u(__floats2half2_rn(x2.x * c0, x2.y * c0));
        a[kc][3] = h2u(__floats2half2_rn(x3.x * c1, x3.y * c1));
    }

    __half* __restrict__ P = g_P[br];
    #pragma unroll
    for (int nt = 0; nt < 16; nt++) {
        float d0 = 0.f, d1 = 0.f, d2 = 0.f, d3 = 0.f;
        const __half* wrow = &Ws[(nt * 8 + g) * WST + tg * 2];
        #pragma unroll
        for (int kc = 0; kc < 8; kc++) {
            unsigned b0 = *reinterpret_cast<const unsigned*>(wrow + kc * 16);
            unsigned b1 = *reinterpret_cast<const unsigned*>(wrow + kc * 16 + 8);
            asm volatile(
                "mma.sync.aligned.m16n8k16.row.col.f32.f16.f16.f32 "
                "{%0,%1,%2,%3}, {%4,%5,%6,%7}, {%8,%9}, {%0,%1,%2,%3};"
                : "+f"(d0), "+f"(d1), "+f"(d2), "+f"(d3)
                : "r"(a[kc][0]), "r"(a[kc][1]), "r"(a[kc][2]), "r"(a[kc][3]),
                  "r"(b0), "r"(b1));
        }
        int col = nt * 8 + tg * 2;
        if (v0) *reinterpret_cast<__half2*>(&P[row0 * 128 + col]) = __floats2half2_rn(d0, d1);
        if (v1) *reinterpret_cast<__half2*>(&P[row1 * 128 + col]) = __floats2half2_rn(d2, d3);
    }
}

// ---------------- gather + epilogue (R5 version: measured best, MLP-4) ----------------
__global__ __launch_bounds__(256) void agg_epilogue_kernel(
        const int* __restrict__ g1, const int* __restrict__ g2,
        const float* __restrict__ bias) {
    int br = blockIdx.y;
    const int* gid = br ? g2 : g1;
    const int w = threadIdx.x >> 5, lane = threadIdx.x & 31;
    const int* __restrict__ off  = g_off[br];
    const int* __restrict__ esrc = g_esrc[br];
    const uint2* __restrict__ Pu = reinterpret_cast<const uint2*>(g_P[br]);
    float* gsum = g_gsum[br];
    int*   gcnt = g_gcnt[br];
    const float4 bv = reinterpret_cast<const float4*>(bias)[lane];

    float4 racc = make_float4(0.f, 0.f, 0.f, 0.f);
    int rcnt = 0;
    int curg = -1;
    const int baseN = blockIdx.x * 256;

    for (int t = 0; t < 32; t++) {
        int node = baseN + t * 8 + w;
        if (node >= NN) break;                      // monotone in t
        int g = gid[node];
        if (g != curg) {
            if (curg >= 0) {
                atomicAdd(&gsum[curg * 128 + lane * 4 + 0], racc.x);
                atomicAdd(&gsum[curg * 128 + lane * 4 + 1], racc.y);
                atomicAdd(&gsum[curg * 128 + lane * 4 + 2], racc.z);
                atomicAdd(&gsum[curg * 128 + lane * 4 + 3], racc.w);
                if (lane == 0) atomicAdd(&gcnt[curg], rcnt);
                racc = make_float4(0.f, 0.f, 0.f, 0.f);
                rcnt = 0;
            }
            curg = g;
        }
        int beg = off[node], end = off[node + 1];
        float ax = 0.f, ay = 0.f, az = 0.f, aw = 0.f;
        int e = beg;
        while (e < end) {
            int cnt = min(32, end - e);
            int sid = (lane < cnt) ? esrc[e + lane] : 0;
            int j = 0;
            for (; j + 4 <= cnt; j += 4) {
                int s0 = __shfl_sync(0xffffffffu, sid, j + 0);
                int s1 = __shfl_sync(0xffffffffu, sid, j + 1);
                int s2 = __shfl_sync(0xffffffffu, sid, j + 2);
                int s3 = __shfl_sync(0xffffffffu, sid, j + 3);
                uint2 v0 = Pu[s0 * 32 + lane];
                uint2 v1 = Pu[s1 * 32 + lane];
                uint2 v2 = Pu[s2 * 32 + lane];
                uint2 v3 = Pu[s3 * 32 + lane];
                #define ACC_V(v) { \
                    const __half2* hp = reinterpret_cast<const __half2*>(&(v)); \
                    float2 fa = __half22float2(hp[0]); \
                    float2 fb = __half22float2(hp[1]); \
                    ax += fa.x; ay += fa.y; az += fb.x; aw += fb.y; }
                ACC_V(v0) ACC_V(v1) ACC_V(v2) ACC_V(v3)
            }
            for (; j < cnt; j++) {
                int s0 = __shfl_sync(0xffffffffu, sid, j);
                uint2 v0 = Pu[s0 * 32 + lane];
                ACC_V(v0)
                #undef ACC_V
            }
            e += cnt;
        }
        float cin = rsqrtf(fmaxf((float)(end - beg), 1.f));
        float hx = ax * cin + bv.x;
        float hy = ay * cin + bv.y;
        float hz = az * cin + bv.z;
        float hw = aw * cin + bv.w;
        float p = hx * hx + hy * hy + hz * hz + hw * hw;
        #pragma unroll
        for (int o = 16; o > 0; o >>= 1) p += __shfl_xor_sync(0xffffffffu, p, o);
        float inv = 1.f / fmaxf(sqrtf(p), 1e-12f);
        racc.x += 1.f / (1.f + __expf(-hx * inv));   // relu(sigmoid)==sigmoid
        racc.y += 1.f / (1.f + __expf(-hy * inv));
        racc.z += 1.f / (1.f + __expf(-hz * inv));
        racc.w += 1.f / (1.f + __expf(-hw * inv));
        rcnt++;
    }
    if (curg >= 0) {
        atomicAdd(&gsum[curg * 128 + lane * 4 + 0], racc.x);
        atomicAdd(&gsum[curg * 128 + lane * 4 + 1], racc.y);
        atomicAdd(&gsum[curg * 128 + lane * 4 + 2], racc.z);
        atomicAdd(&gsum[curg * 128 + lane * 4 + 3], racc.w);
        if (lane == 0) atomicAdd(&gcnt[curg], rcnt);
    }
}

__global__ void final_kernel(const float* __restrict__ Wc, const float* __restrict__ bc,
                             float* __restrict__ out) {
    __shared__ float h1[128], h2[128];
    __shared__ float rsum[2];
    int g = blockIdx.x, t = threadIdx.x;   // 64 threads
    float c1 = fmaxf((float)g_gcnt[0][g], 1.f);
    float c2 = fmaxf((float)g_gcnt[1][g], 1.f);
    for (int k = t; k < 128; k += 64) {
        h1[k] = g_gsum[0][g * 128 + k] / c1;
        h2[k] = g_gsum[1][g * 128 + k] / c2;
    }
    __syncthreads();
    float l1 = bc[t], l2 = bc[t];
    #pragma unroll 4
    for (int k = 0; k < 128; k++) {
        float w = Wc[k * 64 + t];
        l1 = fmaf(h1[k], w, l1);
        l2 = fmaf(h2[k], w, l2);
    }
    float d = l1 - l2 + 1e-6f;
    float sq = d * d;
    for (int o = 16; o > 0; o >>= 1) sq += __shfl_down_sync(0xffffffffu, sq, o);
    if ((t & 31) == 0) rsum[t >> 5] = sq;
    __syncthreads();
    if (t == 0) out[g] = sqrtf(rsum[0] + rsum[1]);
}

// ---------------- launch (R5 topology: CSR chain overlaps GEMM) ----------------
extern "C" void kernel_launch(void* const* d_in, const int* in_sizes, int n_in,
                              void* d_out, int out_size) {
    const float* feat1 = (const float*)d_in[0];
    const float* feat2 = (const float*)d_in[1];
    const int* src1 = (const int*)d_in[2];
    const int* dst1 = (const int*)d_in[3];
    const int* gid1 = (const int*)d_in[4];
    const int* src2 = (const int*)d_in[5];
    const int* dst2 = (const int*)d_in[6];
    const int* gid2 = (const int*)d_in[7];
    const float* W  = (const float*)d_in[8];
    const float* b  = (const float*)d_in[9];
    const float* Wc = (const float*)d_in[10];
    const float* bc = (const float*)d_in[11];
    float* out = (float*)d_out;

    const int EB = (NE + 255) / 256;     // 6250
    const int NB = (NN + 255) / 256;     // 391
    const int GB = (NN + 127) / 128;     // 782
    const int SMEM_MMA = NF * WST * 2;   // 34816 B

    cudaStream_t s2;
    cudaStreamCreateWithFlags(&s2, cudaStreamNonBlocking);
    cudaEvent_t evA, evB;
    cudaEventCreateWithFlags(&evA, cudaEventDisableTiming);
    cudaEventCreateWithFlags(&evB, cudaEventDisableTiming);

    zw_kernel     <<<dim3(NB, 2), 256>>>(W);
    degree_kernel <<<dim3(EB, 2), 256>>>(src1, dst1, src2, dst2);
    cudaEventRecord(evA, 0);

    // CSR chain on side stream (needs deg_in only): single-pass scan + scatter
    cudaStreamWaitEvent(s2, evA, 0);
    scanLB_kernel  <<<dim3(SC_NB, 2), SC_BS, 0, s2>>>();
    scatter_kernel <<<dim3(EB, 2), 256, 0, s2>>>(src1, dst1, src2, dst2);
    cudaEventRecord(evB, s2);

    // GEMM on main stream (needs deg_out + W only) — overlaps the CSR chain
    gemm_mma_kernel<<<dim3(GB, 2), 256, SMEM_MMA>>>(feat1, feat2);

    cudaStreamWaitEvent(0, evB, 0);
    agg_epilogue_kernel<<<dim3(NB, 2), 256>>>(gid1, gid2, b);
    final_kernel  <<<NG, 64>>>(Wc, bc, out);
}